// round 3
// baseline (speedup 1.0000x reference)
#include <cuda_runtime.h>

#define N_NODES   100000
#define E_PER_REL 150000
#define R_REL     4
#define E_TOTAL   (E_PER_REL * R_REL)
#define WC_COLS   320   // [self(64) | rel0(64) | rel1(64) | rel2(64) | rel3(64)]

// Scratch (device globals — no runtime allocation allowed)
__device__ __align__(128) float g_Y1[(size_t)N_NODES * WC_COLS];   // 128 MB
__device__ __align__(128) float g_Y2[(size_t)N_NODES * WC_COLS];   // 128 MB
__device__ __align__(128) float g_Wc1t[WC_COLS * 128];             // transposed [col][k]
__device__ __align__(128) float g_Wc2t[WC_COLS * 64];
__device__ int g_idx_is64;   // 1 if index buffers are int64, 0 if int32

// ---------------------------------------------------------------------------
// Index-dtype sniff: int64 values < 2^31 ⇒ every odd 32-bit word is zero.
// ---------------------------------------------------------------------------
__global__ void sniff_kernel(const unsigned int* __restrict__ idx) {
    __shared__ int nz;
    if (threadIdx.x == 0) nz = 0;
    __syncthreads();
    for (int i = threadIdx.x; i < 4096; i += blockDim.x)
        if (idx[2 * i + 1] != 0u) nz = 1;
    __syncthreads();
    if (threadIdx.x == 0) g_idx_is64 = (nz == 0) ? 1 : 0;
}

// ---------------------------------------------------------------------------
// Build combined TRANSPOSED weights: Wc_t[c][d], c in [0,320):
//   c<64: Wself[d][c];  c>=64: sign_r * Wrel[r][d][o], r=(c-64)/64, o=(c-64)%64
// ---------------------------------------------------------------------------
__global__ void prep_w_kernel(const float* __restrict__ Wrel,
                              const float* __restrict__ Wself,
                              float* __restrict__ Wct, int din) {
    int idx = blockIdx.x * blockDim.x + threadIdx.x;
    int total = din * WC_COLS;
    if (idx >= total) return;
    int d = idx / WC_COLS;
    int c = idx - d * WC_COLS;
    float v;
    if (c < 64) {
        v = Wself[d * 64 + c];
    } else {
        int r = (c - 64) >> 6;
        int o = (c - 64) & 63;
        v = Wrel[((size_t)r * din + d) * 64 + o];
        if (r == 3) v = -v;   // SUBTRACT_REL = 3
    }
    Wct[(size_t)c * din + d] = v;   // transposed
}

// ---------------------------------------------------------------------------
// packed f32x2 FMA (FFMA2) — only reachable via PTX
// ---------------------------------------------------------------------------
__device__ __forceinline__ void ffma2(unsigned long long& acc,
                                      unsigned long long a,
                                      unsigned long long b) {
    asm("fma.rn.f32x2 %0, %1, %2, %0;" : "+l"(acc) : "l"(a), "l"(b));
}

// ---------------------------------------------------------------------------
// GEMM: C[M,320] = A[M,K] @ Wc[K,320], 64-wide column blocks (blockIdx.y).
// TILE_M=128, TILE_N=64. 256 threads, each 8 rows x 4 cols.
// k-paired FFMA2: lane0 accumulates even-k, lane1 odd-k; epilogue adds lanes.
// B comes pre-transposed (Bt[col][k]) so b k-pairs are contiguous.
// RELU applies relu to A on load (fuses layer-1 activation).
// ---------------------------------------------------------------------------
template <int K, bool RELU>
__global__ void __launch_bounds__(256, 2) gemm_kernel(const float* __restrict__ A, int lda,
                                                      const float* __restrict__ Bt,
                                                      float* __restrict__ C) {
    __shared__ float As[128 * 64];       // row-major [row][k], 32 KB
    __shared__ float Bs[64 * 68];        // transposed [col][k], padded, 17.4 KB
    const int m0   = blockIdx.x * 128;
    const int cb   = blockIdx.y;         // column block (0..4)
    const int tid  = threadIdx.x;
    const int tcol = tid & 15;           // 16 col-groups of 4
    const int trow = tid >> 4;           // 16 row-groups of 8

    unsigned long long acc[8][4];
#pragma unroll
    for (int i = 0; i < 8; i++)
#pragma unroll
        for (int j = 0; j < 4; j++) acc[i][j] = 0ull;

    const int bcol = tid >> 2;           // 0..63 (B loader)
    const int bk   = (tid & 3) * 16;     // k offset within tile (B loader)

#pragma unroll 1
    for (int k0 = 0; k0 < K; k0 += 64) {
        // Load A tile [128 x 64] (coalesced float4 along k)
#pragma unroll
        for (int p = 0; p < 8; p++) {
            int row = p * 16 + trow;
            int gr  = m0 + row;
            float4 v = make_float4(0.f, 0.f, 0.f, 0.f);
            if (gr < N_NODES) {
                v = *(const float4*)&A[(size_t)gr * lda + k0 + tcol * 4];
                if (RELU) {
                    v.x = fmaxf(v.x, 0.f); v.y = fmaxf(v.y, 0.f);
                    v.z = fmaxf(v.z, 0.f); v.w = fmaxf(v.w, 0.f);
                }
            }
            *(float4*)&As[row * 64 + tcol * 4] = v;
        }
        // Load B tile transposed: Bs[col][k] from Bt[(cb*64+col)*K + k0+k]
#pragma unroll
        for (int q = 0; q < 4; q++) {
            float4 v = *(const float4*)&Bt[(size_t)(cb * 64 + bcol) * K + k0 + bk + q * 4];
            *(float4*)&Bs[bcol * 68 + bk + q * 4] = v;
        }
        __syncthreads();

#pragma unroll
        for (int kq = 0; kq < 64; kq += 4) {
            ulonglong2 bq[4];
#pragma unroll
            for (int j = 0; j < 4; j++)
                bq[j] = *(const ulonglong2*)&Bs[(tcol * 4 + j) * 68 + kq];
#pragma unroll
            for (int i = 0; i < 8; i++) {
                ulonglong2 aq = *(const ulonglong2*)&As[(trow * 8 + i) * 64 + kq];
#pragma unroll
                for (int j = 0; j < 4; j++) {
                    ffma2(acc[i][j], aq.x, bq[j].x);
                    ffma2(acc[i][j], aq.y, bq[j].y);
                }
            }
        }
        __syncthreads();
    }

#pragma unroll
    for (int i = 0; i < 8; i++) {
        int gr = m0 + trow * 8 + i;
        if (gr < N_NODES) {
            float4 o;
            float2 p0 = *(float2*)&acc[i][0];
            float2 p1 = *(float2*)&acc[i][1];
            float2 p2 = *(float2*)&acc[i][2];
            float2 p3 = *(float2*)&acc[i][3];
            o.x = p0.x + p0.y; o.y = p1.x + p1.y;
            o.z = p2.x + p2.y; o.w = p3.x + p3.y;
            *(float4*)&C[(size_t)gr * WC_COLS + cb * 64 + tcol * 4] = o;
        }
    }
}

// ---------------------------------------------------------------------------
// Scatter: for each edge e of relation r:
//   Y[dst][0:64] += Y[src][64+64r : 128+64r]   (signs pre-folded into Wc)
// 16 threads per edge, one red.global.add.v4.f32 (16B) per thread.
// ---------------------------------------------------------------------------
__global__ void __launch_bounds__(256) scatter_kernel(const void* __restrict__ src_v,
                                                      const void* __restrict__ dst_v,
                                                      float* __restrict__ Y) {
    int gid  = blockIdx.x * blockDim.x + threadIdx.x;
    int edge = gid >> 4;
    if (edge >= E_TOTAL) return;
    int sub = gid & 15;
    int r   = edge / E_PER_REL;          // src/dst are [4][150000] row-major

    long long s, d;
    if (g_idx_is64) {
        s = ((const long long*)src_v)[edge];
        d = ((const long long*)dst_v)[edge];
    } else {
        s = ((const int*)src_v)[edge];
        d = ((const int*)dst_v)[edge];
    }

    const float4 v = *(const float4*)&Y[(size_t)s * WC_COLS + 64 + r * 64 + sub * 4];
    float* p = &Y[(size_t)d * WC_COLS + sub * 4];
    asm volatile("red.global.add.v4.f32 [%0], {%1,%2,%3,%4};"
                 :: "l"(p), "f"(v.x), "f"(v.y), "f"(v.z), "f"(v.w)
                 : "memory");
}

// ---------------------------------------------------------------------------
// out = sigmoid(relu(Y2[:, 0:64]))
// ---------------------------------------------------------------------------
__global__ void __launch_bounds__(256) sigmoid_kernel(const float* __restrict__ Y,
                                                      float* __restrict__ out) {
    int idx = blockIdx.x * blockDim.x + threadIdx.x;   // over N*16 float4s
    if (idx >= N_NODES * 16) return;
    int n  = idx >> 4;
    int c4 = idx & 15;
    float4 v = *(const float4*)&Y[(size_t)n * WC_COLS + c4 * 4];
    v.x = 1.f / (1.f + __expf(-fmaxf(v.x, 0.f)));
    v.y = 1.f / (1.f + __expf(-fmaxf(v.y, 0.f)));
    v.z = 1.f / (1.f + __expf(-fmaxf(v.z, 0.f)));
    v.w = 1.f / (1.f + __expf(-fmaxf(v.w, 0.f)));
    *(float4*)&out[(size_t)n * 64 + c4 * 4] = v;
}

// ---------------------------------------------------------------------------
extern "C" void kernel_launch(void* const* d_in, const int* in_sizes, int n_in,
                              void* d_out, int out_size) {
    const float* node_emb = (const float*)d_in[0];      // [100000,128] f32
    const void*  src      = d_in[1];                    // [4,150000] int32/int64
    const void*  dst      = d_in[2];                    // [4,150000]
    const float* W1       = (const float*)d_in[3];      // [4,128,64]
    const float* Wself1   = (const float*)d_in[4];      // [128,64]
    const float* W2       = (const float*)d_in[5];      // [4,64,64]
    const float* Wself2   = (const float*)d_in[6];      // [64,64]
    float*       out      = (float*)d_out;              // [100000,64]

    float *Y1, *Y2, *Wc1t, *Wc2t;
    cudaGetSymbolAddress((void**)&Y1, g_Y1);
    cudaGetSymbolAddress((void**)&Y2, g_Y2);
    cudaGetSymbolAddress((void**)&Wc1t, g_Wc1t);
    cudaGetSymbolAddress((void**)&Wc2t, g_Wc2t);

    // Detect index dtype (writes g_idx_is64)
    sniff_kernel<<<1, 256>>>((const unsigned int*)src);

    // Weight prep (tiny; writes transposed weights)
    prep_w_kernel<<<(128 * WC_COLS + 255) / 256, 256>>>(W1, Wself1, Wc1t, 128);
    prep_w_kernel<<<(64 * WC_COLS + 255) / 256, 256>>>(W2, Wself2, Wc2t, 64);

    const int mblocks = (N_NODES + 127) / 128;   // 782
    const int sblocks = (E_TOTAL * 16 + 255) / 256;

    // Layer 1: Y1 = node_emb @ Wc1; scatter messages into Y1[:,0:64]
    gemm_kernel<128, false><<<dim3(mblocks, 5), 256>>>(node_emb, 128, Wc1t, Y1);
    scatter_kernel<<<sblocks, 256>>>(src, dst, Y1);

    // Layer 2: Y2 = relu(Y1[:,0:64]) @ Wc2; scatter into Y2[:,0:64]
    gemm_kernel<64, true><<<dim3(mblocks, 5), 256>>>(Y1, WC_COLS, Wc2t, Y2);
    scatter_kernel<<<sblocks, 256>>>(src, dst, Y2);

    // out = sigmoid(relu(Y2[:,0:64]))
    sigmoid_kernel<<<(N_NODES * 16 + 255) / 256, 256>>>(Y2, out);
}

// round 5
// speedup vs baseline: 2.1184x; 2.1184x over previous
#include <cuda_runtime.h>
#include <cuda_bf16.h>
#include <cstdint>

#define N_NODES   100000
#define E_PER_REL 150000
#define R_REL     4
#define E_TOTAL   (E_PER_REL * R_REL)
#define WC_COLS   320   // [self(64) | rel0(64) | rel1(64) | rel2(64) | rel3(64)]

// ---------------------------------------------------------------------------
// Device globals (no runtime allocation allowed)
// ---------------------------------------------------------------------------
__device__ __align__(128) float g_Y1[(size_t)N_NODES * WC_COLS];   // 128 MB
__device__ __align__(128) float g_Y2[(size_t)N_NODES * WC_COLS];   // 128 MB
// Pre-swizzled bf16 weight tiles: [cb*CHUNKS+ch] tiles of 64n x 64k (8192 B),
// 16B-granule XOR swizzle identical to the kernel's smem image.
__device__ __align__(256) __nv_bfloat16 g_B1h[5 * 2 * 64 * 64];
__device__ __align__(256) __nv_bfloat16 g_B1l[5 * 2 * 64 * 64];
__device__ __align__(256) __nv_bfloat16 g_B2h[5 * 1 * 64 * 64];
__device__ __align__(256) __nv_bfloat16 g_B2l[5 * 1 * 64 * 64];
__device__ int g_idx_is64;

// XOR swizzle on 16B granules within a 128B row: byte offset for (row, k)
__device__ __forceinline__ uint32_t swz(uint32_t row, uint32_t k) {
    uint32_t g = k >> 3;
    return row * 128u + (((g ^ (row & 7u)) << 4) | ((k & 7u) << 1));
}

// ---------------------------------------------------------------------------
// Index-dtype sniff: int64 values < 2^31 => every odd 32-bit word is zero.
// ---------------------------------------------------------------------------
__global__ void sniff_kernel(const unsigned int* __restrict__ idx) {
    __shared__ int nz;
    if (threadIdx.x == 0) nz = 0;
    __syncthreads();
    for (int i = threadIdx.x; i < 4096; i += blockDim.x)
        if (idx[2 * i + 1] != 0u) nz = 1;
    __syncthreads();
    if (threadIdx.x == 0) g_idx_is64 = (nz == 0) ? 1 : 0;
}

// ---------------------------------------------------------------------------
// Weight prep: combined signed weights -> swizzled bf16 hi/lo tiles.
// Tile (cb, ch) holds B[n=cb*64..][k-chunk ch], [64n x 64k], k contiguous
// per n ("col" operand layout for mma.row.col), XOR-swizzled.
// ---------------------------------------------------------------------------
__global__ void prep_w_kernel(const float* __restrict__ Wrel,
                              const float* __restrict__ Wself,
                              __nv_bfloat16* __restrict__ Bh,
                              __nv_bfloat16* __restrict__ Bl,
                              int din, int chunks) {
    int idx = blockIdx.x * blockDim.x + threadIdx.x;   // c * din + d
    if (idx >= WC_COLS * din) return;
    int c = idx / din;
    int d = idx - c * din;
    float v;
    if (c < 64) {
        v = Wself[d * 64 + c];
    } else {
        int r = (c - 64) >> 6;
        int o = (c - 64) & 63;
        v = Wrel[((size_t)r * din + d) * 64 + o];
        if (r == 3) v = -v;   // SUBTRACT_REL = 3
    }
    __nv_bfloat16 hi = __float2bfloat16(v);
    __nv_bfloat16 lo = __float2bfloat16(v - __bfloat162float(hi));
    int cb = c >> 6, n = c & 63;
    int ch = d >> 6, k = d & 63;
    size_t tile = (size_t)(cb * chunks + ch) * 8192;   // bytes
    uint32_t off = swz((uint32_t)n, (uint32_t)k);
    *(__nv_bfloat16*)((char*)Bh + tile + off) = hi;
    *(__nv_bfloat16*)((char*)Bl + tile + off) = lo;
}

// ---------------------------------------------------------------------------
// mma.sync m16n8k16 bf16 (row.col), f32 accumulate — base PTX, works on sm_103
// ---------------------------------------------------------------------------
__device__ __forceinline__ void mma16816(float* c, const uint32_t* a, uint32_t b0, uint32_t b1) {
    asm volatile("mma.sync.aligned.m16n8k16.row.col.f32.bf16.bf16.f32 "
                 "{%0,%1,%2,%3}, {%4,%5,%6,%7}, {%8,%9}, {%0,%1,%2,%3};"
                 : "+f"(c[0]), "+f"(c[1]), "+f"(c[2]), "+f"(c[3])
                 : "r"(a[0]), "r"(a[1]), "r"(a[2]), "r"(a[3]), "r"(b0), "r"(b1));
}
__device__ __forceinline__ void ldsm4(uint32_t* r, uint32_t addr) {
    asm volatile("ldmatrix.sync.aligned.m8n8.x4.shared.b16 {%0,%1,%2,%3}, [%4];"
                 : "=r"(r[0]), "=r"(r[1]), "=r"(r[2]), "=r"(r[3]) : "r"(addr));
}

// ---------------------------------------------------------------------------
// Tensor-core GEMM: C[M,320] = A[M, CHUNKS*64] @ Wc. CTA: 128m x 64n (cb).
// 8 warps, each 16m x 64n. bf16 3-MMA split, f32 accum in registers.
// ---------------------------------------------------------------------------
template <int CHUNKS, bool RELU>
__global__ void __launch_bounds__(256, 2) gemm_mma_kernel(const float* __restrict__ A, int lda,
                                                          const __nv_bfloat16* __restrict__ Bh,
                                                          const __nv_bfloat16* __restrict__ Bl,
                                                          float* __restrict__ C) {
    __shared__ __nv_bfloat16 Ah[128 * 64];   // 16 KB, swizzled
    __shared__ __nv_bfloat16 Al[128 * 64];   // 16 KB
    __shared__ __nv_bfloat16 Bhs[64 * 64];   // 8 KB
    __shared__ __nv_bfloat16 Bls[64 * 64];   // 8 KB

    const int tid  = threadIdx.x;
    const int wid  = tid >> 5;
    const int lane = tid & 31;
    const int m0   = blockIdx.x * 128;
    const int cb   = blockIdx.y;
    const int wrow = wid * 16;

    const uint32_t ah_u = (uint32_t)__cvta_generic_to_shared(Ah);
    const uint32_t al_u = (uint32_t)__cvta_generic_to_shared(Al);
    const uint32_t bh_u = (uint32_t)__cvta_generic_to_shared(Bhs);
    const uint32_t bl_u = (uint32_t)__cvta_generic_to_shared(Bls);

    // ldmatrix lane geometry
    const int tq = lane >> 3;           // which 8x8 tile this lane addresses
    const int lr = lane & 7;
    const int a_row = wrow + lr + (tq & 1) * 8;     // a0:m0-7 a1:m8-15 a2/a3: k+8
    const int a_gad = (tq >> 1);                    // +1 granule for k8-15
    const int b_lr  = lr + (tq >> 1) * 8;           // n within pair (0-15)
    const int b_gad = (tq & 1);                     // k8-15 granule

    float acc[8][4];
#pragma unroll
    for (int i = 0; i < 8; i++)
#pragma unroll
        for (int j = 0; j < 4; j++) acc[i][j] = 0.f;

    for (int ch = 0; ch < CHUNKS; ch++) {
        // ---- Copy pre-swizzled B tiles (8 KB hi + 8 KB lo)
        {
            size_t tile = (size_t)(cb * CHUNKS + ch) * 8192;
            const uint4* sh = (const uint4*)((const char*)Bh + tile);
            const uint4* sl = (const uint4*)((const char*)Bl + tile);
            uint4* dh = (uint4*)Bhs;
            uint4* dl = (uint4*)Bls;
#pragma unroll
            for (int i = 0; i < 2; i++) {
                int g = i * 256 + tid;
                dh[g] = sh[g];
                dl[g] = sl[g];
            }
        }
        // ---- Load + convert A tile [128m x 64k] f32 -> bf16 hi/lo, swizzled
#pragma unroll
        for (int i = 0; i < 4; i++) {
            int gran = i * 256 + tid;       // 1024 granules of 8 k-values
            int m = gran >> 3;
            int g = gran & 7;
            int gr = m0 + m;
            float4 v0 = make_float4(0.f, 0.f, 0.f, 0.f), v1 = v0;
            if (gr < N_NODES) {
                const float* ap = &A[(size_t)gr * lda + ch * 64 + g * 8];
                v0 = *(const float4*)ap;
                v1 = *(const float4*)(ap + 4);
                if (RELU) {
                    v0.x = fmaxf(v0.x, 0.f); v0.y = fmaxf(v0.y, 0.f);
                    v0.z = fmaxf(v0.z, 0.f); v0.w = fmaxf(v0.w, 0.f);
                    v1.x = fmaxf(v1.x, 0.f); v1.y = fmaxf(v1.y, 0.f);
                    v1.z = fmaxf(v1.z, 0.f); v1.w = fmaxf(v1.w, 0.f);
                }
            }
            float f[8] = {v0.x, v0.y, v0.z, v0.w, v1.x, v1.y, v1.z, v1.w};
            __nv_bfloat16 h[8], l[8];
#pragma unroll
            for (int j = 0; j < 8; j++) {
                h[j] = __float2bfloat16(f[j]);
                l[j] = __float2bfloat16(f[j] - __bfloat162float(h[j]));
            }
            uint32_t off = swz((uint32_t)m, (uint32_t)(g * 8));
            *(uint4*)((char*)Ah + off) = *(const uint4*)h;
            *(uint4*)((char*)Al + off) = *(const uint4*)l;
        }
        __syncthreads();

        // ---- Compute: 4 k-steps of 16
#pragma unroll
        for (int ks = 0; ks < 4; ks++) {
            const uint32_t a_off = a_row * 128u + (((uint32_t)((ks * 2 + a_gad) ^ (a_row & 7))) << 4);
            uint32_t afh[4], afl[4];
            ldsm4(afh, ah_u + a_off);
            ldsm4(afl, al_u + a_off);
#pragma unroll
            for (int ntp = 0; ntp < 4; ntp++) {
                int brow = ntp * 16 + b_lr;
                const uint32_t b_off = brow * 128u + (((uint32_t)((ks * 2 + b_gad) ^ (brow & 7))) << 4);
                uint32_t bfh[4], bfl[4];
                ldsm4(bfh, bh_u + b_off);
                ldsm4(bfl, bl_u + b_off);
                mma16816(acc[2 * ntp + 0], afh, bfh[0], bfh[1]);
                mma16816(acc[2 * ntp + 0], afh, bfl[0], bfl[1]);
                mma16816(acc[2 * ntp + 0], afl, bfh[0], bfh[1]);
                mma16816(acc[2 * ntp + 1], afh, bfh[2], bfh[3]);
                mma16816(acc[2 * ntp + 1], afh, bfl[2], bfl[3]);
                mma16816(acc[2 * ntp + 1], afl, bfh[2], bfh[3]);
            }
        }
        __syncthreads();
    }

    // ---- Epilogue: C frag layout -> direct float2 stores
    const int crow = wrow + (lane >> 2);
    const int ccol = (lane & 3) * 2;
#pragma unroll
    for (int nt = 0; nt < 8; nt++) {
        int gc = cb * 64 + nt * 8 + ccol;
        int gr0 = m0 + crow;
        int gr1 = gr0 + 8;
        if (gr0 < N_NODES)
            *(float2*)&C[(size_t)gr0 * WC_COLS + gc] = make_float2(acc[nt][0], acc[nt][1]);
        if (gr1 < N_NODES)
            *(float2*)&C[(size_t)gr1 * WC_COLS + gc] = make_float2(acc[nt][2], acc[nt][3]);
    }
}

// ---------------------------------------------------------------------------
// Scatter: Y[dst][0:64] += Y[src][64+64r : 128+64r]  (signs pre-folded)
// 16 threads/edge, one red.global.add.v4.f32 each.
// ---------------------------------------------------------------------------
__global__ void __launch_bounds__(256) scatter_kernel(const void* __restrict__ src_v,
                                                      const void* __restrict__ dst_v,
                                                      float* __restrict__ Y) {
    int gid  = blockIdx.x * blockDim.x + threadIdx.x;
    int edge = gid >> 4;
    if (edge >= E_TOTAL) return;
    int sub = gid & 15;
    int r   = edge / E_PER_REL;

    long long s, d;
    if (g_idx_is64) {
        s = ((const long long*)src_v)[edge];
        d = ((const long long*)dst_v)[edge];
    } else {
        s = ((const int*)src_v)[edge];
        d = ((const int*)dst_v)[edge];
    }
    const float4 v = *(const float4*)&Y[(size_t)s * WC_COLS + 64 + r * 64 + sub * 4];
    float* p = &Y[(size_t)d * WC_COLS + sub * 4];
    asm volatile("red.global.add.v4.f32 [%0], {%1,%2,%3,%4};"
                 :: "l"(p), "f"(v.x), "f"(v.y), "f"(v.z), "f"(v.w) : "memory");
}

// ---------------------------------------------------------------------------
// out = sigmoid(relu(Y2[:, 0:64]))
// ---------------------------------------------------------------------------
__global__ void __launch_bounds__(256) sigmoid_kernel(const float* __restrict__ Y,
                                                      float* __restrict__ out) {
    int idx = blockIdx.x * blockDim.x + threadIdx.x;
    if (idx >= N_NODES * 16) return;
    int n  = idx >> 4;
    int c4 = idx & 15;
    float4 v = *(const float4*)&Y[(size_t)n * WC_COLS + c4 * 4];
    v.x = 1.f / (1.f + __expf(-fmaxf(v.x, 0.f)));
    v.y = 1.f / (1.f + __expf(-fmaxf(v.y, 0.f)));
    v.z = 1.f / (1.f + __expf(-fmaxf(v.z, 0.f)));
    v.w = 1.f / (1.f + __expf(-fmaxf(v.w, 0.f)));
    *(float4*)&out[(size_t)n * 64 + c4 * 4] = v;
}

// ---------------------------------------------------------------------------
extern "C" void kernel_launch(void* const* d_in, const int* in_sizes, int n_in,
                              void* d_out, int out_size) {
    const float* node_emb = (const float*)d_in[0];
    const void*  src      = d_in[1];
    const void*  dst      = d_in[2];
    const float* W1       = (const float*)d_in[3];
    const float* Wself1   = (const float*)d_in[4];
    const float* W2       = (const float*)d_in[5];
    const float* Wself2   = (const float*)d_in[6];
    float*       out      = (float*)d_out;

    float *Y1, *Y2;
    __nv_bfloat16 *B1h, *B1l, *B2h, *B2l;
    cudaGetSymbolAddress((void**)&Y1, g_Y1);
    cudaGetSymbolAddress((void**)&Y2, g_Y2);
    cudaGetSymbolAddress((void**)&B1h, g_B1h);
    cudaGetSymbolAddress((void**)&B1l, g_B1l);
    cudaGetSymbolAddress((void**)&B2h, g_B2h);
    cudaGetSymbolAddress((void**)&B2l, g_B2l);

    sniff_kernel<<<1, 256>>>((const unsigned int*)src);
    prep_w_kernel<<<(WC_COLS * 128 + 255) / 256, 256>>>(W1, Wself1, B1h, B1l, 128, 2);
    prep_w_kernel<<<(WC_COLS * 64 + 255) / 256, 256>>>(W2, Wself2, B2h, B2l, 64, 1);

    const int mblocks = (N_NODES + 127) / 128;   // 782
    const int sblocks = (E_TOTAL * 16 + 255) / 256;

    // Layer 1: Y1 = node_emb @ Wc1; scatter messages into Y1[:,0:64]
    gemm_mma_kernel<2, false><<<dim3(mblocks, 5), 256>>>(node_emb, 128, B1h, B1l, Y1);
    scatter_kernel<<<sblocks, 256>>>(src, dst, Y1);

    // Layer 2: Y2 = relu(Y1[:,0:64]) @ Wc2; scatter into Y2[:,0:64]
    gemm_mma_kernel<1, true><<<dim3(mblocks, 5), 256>>>(Y1, WC_COLS, B2h, B2l, Y2);
    scatter_kernel<<<sblocks, 256>>>(src, dst, Y2);

    // out = sigmoid(relu(Y2[:,0:64]))
    sigmoid_kernel<<<(N_NODES * 16 + 255) / 256, 256>>>(Y2, out);
}